// round 1
// baseline (speedup 1.0000x reference)
#include <cuda_runtime.h>
#include <cstdint>

// AF2dMADEBlock: autoregressive flow inversion via exact sequential raster sweep.
// The reference's 64-iteration fixed-point scan is mathematically identical to a
// single raster-order sequential pass because the PixelCNN masks zero all
// contributions from pixels >= current (mask A excludes center at layer 0).
//
// Grid: 64 CTAs = 32 batches x 2 nets (cluster of 2: rank0 = mu, rank1 = lv).
// 512 threads/CTA. Masked w1/w2 weights (5 taps x 64 in x 64 out) live in
// registers (80 float regs/thread); activations gathered into contiguous smem
// buffers and read with a conflict-free broadcast pattern.
// Per-pixel mu/logstd exchange between the two CTAs of a cluster via DSMEM
// stores + double-buffered mbarriers.

#define ELU_EPS 1e-12f

__device__ __forceinline__ uint32_t smem_u32(const void* p){
  return (uint32_t)__cvta_generic_to_shared((void*)p);
}

__global__ void __cluster_dims__(2,1,1) __launch_bounds__(512,1)
made_flow_kernel(const float* __restrict__ xg,
  const float* __restrict__ mw0, const float* __restrict__ mb0,
  const float* __restrict__ mw1, const float* __restrict__ mb1,
  const float* __restrict__ mw2, const float* __restrict__ mb2,
  const float* __restrict__ mwo, const float* __restrict__ mbo,
  const float* __restrict__ lw0, const float* __restrict__ lb0,
  const float* __restrict__ lw1, const float* __restrict__ lb1,
  const float* __restrict__ lw2, const float* __restrict__ lb2,
  const float* __restrict__ lwo, const float* __restrict__ lbo,
  float* __restrict__ out, int out_n)
{
  __shared__ __align__(16) float h0g[64*64];   // h0 over full 8x8 grid, [pix][ch]
  __shared__ __align__(16) float h1g[64*64];   // h1 over full 8x8 grid
  __shared__ __align__(16) float w0s[16*64];   // packed mask-A w0: [(tap*4+ic)][o]
  __shared__ __align__(16) float y_s[64*4];    // y, [pix][ch]
  __shared__ __align__(16) float x_s[64*4];    // x, [pix][ch]
  __shared__ __align__(16) float a_l1[320];    // gathered input window for layer1
  __shared__ __align__(16) float a_l2[320];    // gathered input window for layer2
  __shared__ __align__(16) float h2_s[64];
  __shared__ float b0s[64], b1s[64], b2s[64];
  __shared__ __align__(16) float wos[256];     // 1x1 out conv [oc][c]
  __shared__ float bos[4];
  __shared__ __align__(16) float myout[4];     // this net's 4 outputs at pixel p
  __shared__ __align__(16) float recvbuf[2][4];// peer's 4 outputs, dbl-buffered
  __shared__ __align__(8) unsigned long long mbar[2];

  const int tid = threadIdx.x;
  uint32_t rank; asm("mov.u32 %0, %%cluster_ctarank;" : "=r"(rank));
  const int batch = blockIdx.x >> 1;

  const float* w0g = rank ? lw0 : mw0;
  const float* b0g = rank ? lb0 : mb0;
  const float* w1g = rank ? lw1 : mw1;
  const float* b1g = rank ? lb1 : mb1;
  const float* w2g = rank ? lw2 : mw2;
  const float* b2g = rank ? lb2 : mb2;
  const float* wog = rank ? lwo : mwo;
  const float* bog = rank ? lbo : mbo;

  if (tid == 0){
    asm volatile("mbarrier.init.shared.b64 [%0], %1;"
                 :: "r"(smem_u32(&mbar[0])), "r"(1u) : "memory");
    asm volatile("mbarrier.init.shared.b64 [%0], %1;"
                 :: "r"(smem_u32(&mbar[1])), "r"(1u) : "memory");
  }

  // ---- Stage weights/biases/x into smem ----
  // w0 packed: tap t in {(-1,-1),(-1,0),(-1,1),(0,-1)} (mask A), transposed so
  // lanes (o consecutive) read conflict-free.
  for (int idx = tid; idx < 1024; idx += 512){
    int r = idx >> 6, o = idx & 63;
    int t = r >> 2, ic = r & 3;
    int ky = (t == 3) ? 1 : 0;
    int kx = (t == 3) ? 0 : t;
    w0s[idx] = w0g[(o*4 + ic)*9 + ky*3 + kx];
  }
  if (tid < 64){ b0s[tid] = b0g[tid]; b1s[tid] = b1g[tid]; b2s[tid] = b2g[tid]; }
  if (tid < 256) wos[tid] = wog[tid];
  if (tid < 4)   bos[tid] = bog[tid];
  if (tid < 256){
    int pos = tid & 63, c = tid >> 6;
    x_s[pos*4 + c] = xg[batch*256 + tid];   // NCHW -> [pix][ch]
  }

  // ---- Masked mask-B weights into registers ----
  // Thread (o = tid>>3, j = tid&7) owns K-slice {4j+32i+m : i<10, m<4} of the
  // 320-long dot for output channel o. k -> (tap = k>>6, ic = k&63);
  // taps in order (-1,-1),(-1,0),(-1,1),(0,-1),(0,0).
  const int o = tid >> 3;
  const int j = tid & 7;
  float4 w1r[10], w2r[10];
  #pragma unroll
  for (int i = 0; i < 10; i++){
    float t1[4], t2[4];
    #pragma unroll
    for (int m = 0; m < 4; m++){
      int k  = (j << 2) + (i << 5) + m;
      int t  = k >> 6, ic = k & 63;
      int ky = (t >= 3) ? 1 : 0;
      int kx = (t >= 3) ? (t - 3) : t;
      int gi = (o*64 + ic)*9 + ky*3 + kx;
      t1[m] = w1g[gi];
      t2[m] = w2g[gi];
    }
    w1r[i] = make_float4(t1[0], t1[1], t1[2], t1[3]);
    w2r[i] = make_float4(t2[0], t2[1], t2[2], t2[3]);
  }

  __syncthreads();
  // mbarrier init must be cluster-visible before any peer arrive.
  asm volatile("barrier.cluster.arrive.aligned;" ::: "memory");
  asm volatile("barrier.cluster.wait.aligned;"   ::: "memory");

  float lssum = 0.f;

  for (int p = 0; p < 64; p++){
    const int py = p >> 3, px = p & 7;

    // ---- Phase 1: h0[p] (threads 0..63) + past-tap gathers (threads 64..191)
    if (tid < 64){
      float acc = b0s[tid];
      #pragma unroll
      for (int t = 0; t < 4; t++){
        int qy = py + ((t < 3) ? -1 : 0);
        int qx = px + ((t < 3) ? (t - 1) : -1);
        if ((unsigned)qy < 8u && (unsigned)qx < 8u){
          int q = qy*8 + qx;
          const float* ww = &w0s[(t << 2)*64 + tid];
          const float* yy = &y_s[q << 2];
          acc = fmaf(ww[0],   yy[0], acc);
          acc = fmaf(ww[64],  yy[1], acc);
          acc = fmaf(ww[128], yy[2], acc);
          acc = fmaf(ww[192], yy[3], acc);
        }
      }
      float e = acc > 0.f ? acc : expm1f(acc);
      h0g[(p << 6) + tid] = e;
      a_l1[256 + tid] = e;            // center tap of layer-1 window
    } else if (tid < 192){
      int idx = tid - 64;             // 128 float4 gathers: 64 for a_l1, 64 for a_l2
      int buf = idx >> 6;
      int v   = idx & 63;
      int t   = v >> 4, c4 = (v & 15) << 2;
      int qy = py + ((t < 3) ? -1 : 0);
      int qx = px + ((t < 3) ? (t - 1) : -1);
      float4 val = make_float4(0.f, 0.f, 0.f, 0.f);
      const float* src = buf ? h1g : h0g;
      if ((unsigned)qy < 8u && (unsigned)qx < 8u)
        val = *(const float4*)&src[((qy*8 + qx) << 6) + c4];
      float* dst = buf ? a_l2 : a_l1;
      *(float4*)&dst[(t << 6) + c4] = val;
    }
    __syncthreads();

    // ---- Phase 2: h1[p] = ELU(W1 . a_l1 + b1), all 512 threads
    {
      float acc0 = 0.f, acc1 = 0.f;
      #pragma unroll
      for (int i = 0; i < 10; i += 2){
        float4 a = *(const float4*)&a_l1[(j << 2) + (i << 5)];
        float4 b = *(const float4*)&a_l1[(j << 2) + ((i + 1) << 5)];
        acc0 = fmaf(w1r[i].x,   a.x, acc0);
        acc0 = fmaf(w1r[i].y,   a.y, acc0);
        acc0 = fmaf(w1r[i].z,   a.z, acc0);
        acc0 = fmaf(w1r[i].w,   a.w, acc0);
        acc1 = fmaf(w1r[i+1].x, b.x, acc1);
        acc1 = fmaf(w1r[i+1].y, b.y, acc1);
        acc1 = fmaf(w1r[i+1].z, b.z, acc1);
        acc1 = fmaf(w1r[i+1].w, b.w, acc1);
      }
      float acc = acc0 + acc1;
      acc += __shfl_down_sync(0xffffffffu, acc, 4, 8);
      acc += __shfl_down_sync(0xffffffffu, acc, 2, 8);
      acc += __shfl_down_sync(0xffffffffu, acc, 1, 8);
      if (j == 0){
        float v = b1s[o] + acc;
        float e = v > 0.f ? v : expm1f(v);
        h1g[(p << 6) + o] = e;
        a_l2[256 + o] = e;            // center tap of layer-2 window
      }
    }
    __syncthreads();

    // ---- Phase 3: h2[p] = ELU(W2 . a_l2 + b2)
    {
      float acc0 = 0.f, acc1 = 0.f;
      #pragma unroll
      for (int i = 0; i < 10; i += 2){
        float4 a = *(const float4*)&a_l2[(j << 2) + (i << 5)];
        float4 b = *(const float4*)&a_l2[(j << 2) + ((i + 1) << 5)];
        acc0 = fmaf(w2r[i].x,   a.x, acc0);
        acc0 = fmaf(w2r[i].y,   a.y, acc0);
        acc0 = fmaf(w2r[i].z,   a.z, acc0);
        acc0 = fmaf(w2r[i].w,   a.w, acc0);
        acc1 = fmaf(w2r[i+1].x, b.x, acc1);
        acc1 = fmaf(w2r[i+1].y, b.y, acc1);
        acc1 = fmaf(w2r[i+1].z, b.z, acc1);
        acc1 = fmaf(w2r[i+1].w, b.w, acc1);
      }
      float acc = acc0 + acc1;
      acc += __shfl_down_sync(0xffffffffu, acc, 4, 8);
      acc += __shfl_down_sync(0xffffffffu, acc, 2, 8);
      acc += __shfl_down_sync(0xffffffffu, acc, 1, 8);
      if (j == 0){
        float v = b2s[o] + acc;
        h2_s[o] = v > 0.f ? v : expm1f(v);
      }
    }
    __syncthreads();

    // ---- Phase 4: 1x1 output conv (4 warps, one per out channel)
    if (tid < 128){
      int oc = tid >> 5, l = tid & 31;
      float partial = wos[oc*64 + l] * h2_s[l];
      partial = fmaf(wos[oc*64 + 32 + l], h2_s[32 + l], partial);
      partial += __shfl_down_sync(0xffffffffu, partial, 16, 32);
      partial += __shfl_down_sync(0xffffffffu, partial,  8, 32);
      partial += __shfl_down_sync(0xffffffffu, partial,  4, 32);
      partial += __shfl_down_sync(0xffffffffu, partial,  2, 32);
      partial += __shfl_down_sync(0xffffffffu, partial,  1, 32);
      if (l == 0){
        float v = bos[oc] + partial;
        if (rank) v *= 0.5f;          // logstd = made_output * 0.5
        myout[oc] = v;
      }
    }
    __syncthreads();

    // ---- Phase 5: exchange with partner CTA, then y[p] update
    const int par = p & 1;
    if (tid == 0){
      unsigned long long v0 = *(const unsigned long long*)&myout[0];
      unsigned long long v1 = *(const unsigned long long*)&myout[2];
      uint32_t peer = rank ^ 1u;
      uint32_t lbuf = smem_u32(&recvbuf[par][0]);
      uint32_t rbuf, rbar;
      asm volatile("mapa.shared::cluster.u32 %0, %1, %2;"
                   : "=r"(rbuf) : "r"(lbuf), "r"(peer));
      asm volatile("st.shared::cluster.b64 [%0], %1;"
                   :: "r"(rbuf), "l"(v0) : "memory");
      asm volatile("st.shared::cluster.b64 [%0], %1;"
                   :: "r"(rbuf + 8), "l"(v1) : "memory");
      uint32_t lbar = smem_u32(&mbar[par]);
      asm volatile("mapa.shared::cluster.u32 %0, %1, %2;"
                   : "=r"(rbar) : "r"(lbar), "r"(peer));
      asm volatile("mbarrier.arrive.release.cluster.shared::cluster.b64 _, [%0];"
                   :: "r"(rbar) : "memory");
      if (rank) lssum += myout[0] + myout[1] + myout[2] + myout[3];
    }
    if (tid < 4){
      uint32_t lbar = smem_u32(&mbar[par]);
      uint32_t phase = (uint32_t)((p >> 1) & 1);
      uint32_t done;
      do {
        asm volatile("{\n\t.reg .pred p;\n\t"
          "mbarrier.try_wait.parity.acquire.cluster.shared::cta.b64 p, [%1], %2, 0x989680;\n\t"
          "selp.b32 %0, 1, 0, p;\n\t}"
          : "=r"(done) : "r"(lbar), "r"(phase) : "memory");
      } while (!done);
      float other = recvbuf[par][tid];
      float mu_v = rank ? other      : myout[tid];
      float ls_v = rank ? myout[tid] : other;
      y_s[(p << 2) + tid] = (x_s[(p << 2) + tid] - mu_v) / (expf(ls_v) + ELU_EPS);
    }
    __syncthreads();
  }

  // ---- Outputs: y (rank 0) in NCHW, per-batch logstd sum (rank 1)
  if (rank == 0){
    for (int idx = tid; idx < 256; idx += 512){
      out[batch*256 + idx] = y_s[((idx & 63) << 2) + (idx >> 6)];
    }
  } else if (tid == 0 && out_n >= 8224){
    out[8192 + batch] = lssum;
  }

  asm volatile("barrier.cluster.arrive.aligned;" ::: "memory");
  asm volatile("barrier.cluster.wait.aligned;"   ::: "memory");
}

extern "C" void kernel_launch(void* const* d_in, const int* in_sizes, int n_in,
                              void* d_out, int out_size) {
  const float* p[17];
  for (int i = 0; i < 17 && i < n_in; i++) p[i] = (const float*)d_in[i];
  made_flow_kernel<<<64, 512>>>(
    p[0],
    p[1], p[2], p[3], p[4], p[5], p[6], p[7], p[8],
    p[9], p[10], p[11], p[12], p[13], p[14], p[15], p[16],
    (float*)d_out, out_size);
}